// round 4
// baseline (speedup 1.0000x reference)
#include <cuda_runtime.h>
#include <cuda_bf16.h>
#include <cstdint>
#include <cstddef>

// ---------------------------------------------------------------------------
// Problem constants
// ---------------------------------------------------------------------------
#define BB_ 4
#define TT_ 4096
#define DD_ 1024
#define MM_ (BB_ * TT_)   // 16384 rows
#define E3_ (3 * DD_)     // 3072

// ---------------------------------------------------------------------------
// Scratch (static device globals -- allocation-free rule)
// ---------------------------------------------------------------------------
__device__ float g_qkv[(size_t)MM_ * E3_];
__device__ __nv_bfloat16 g_x_hi[(size_t)MM_ * DD_];        // reused as A2 hi
__device__ __nv_bfloat16 g_x_lo[(size_t)MM_ * DD_];        // reused as A2 lo
__device__ __nv_bfloat16 g_wq_hi[(size_t)E3_ * DD_];
__device__ __nv_bfloat16 g_wq_lo[(size_t)E3_ * DD_];
__device__ __nv_bfloat16 g_wo_hi[(size_t)DD_ * DD_];
__device__ __nv_bfloat16 g_wo_lo[(size_t)DD_ * DD_];
__device__ float g_invq[MM_];
__device__ float g_kv[BB_ * DD_];
__device__ int   g_mask_is_byte;
__device__ unsigned int g_ticket[2];

// ---------------------------------------------------------------------------
// Helpers (sm_103 baseline ISA: cp.async, ldmatrix, mma.sync)
// ---------------------------------------------------------------------------
__device__ __forceinline__ uint32_t smem_to_u32(const void* smem_ptr) {
    uint32_t addr;
    asm("{ .reg .u64 tmp; cvta.to.shared.u64 tmp, %1; cvt.u32.u64 %0, tmp; }"
        : "=r"(addr) : "l"(smem_ptr));
    return addr;
}

__device__ __forceinline__ void cp16(uint32_t smem_dst, const void* gmem_src) {
    asm volatile("cp.async.cg.shared.global [%0], [%1], 16;\n"
                 :: "r"(smem_dst), "l"(gmem_src));
}
#define CP_ASYNC_COMMIT() asm volatile("cp.async.commit_group;\n" ::: "memory")
#define CP_ASYNC_WAIT_1() asm volatile("cp.async.wait_group 1;\n" ::: "memory")
#define CP_ASYNC_WAIT_0() asm volatile("cp.async.wait_group 0;\n" ::: "memory")

#define LDSM_X4(r0, r1, r2, r3, addr) \
    asm volatile("ldmatrix.sync.aligned.m8n8.x4.shared.b16 {%0,%1,%2,%3}, [%4];" \
                 : "=r"(r0), "=r"(r1), "=r"(r2), "=r"(r3) : "r"(addr))

#define MMA_16816(c, a, b) \
    asm volatile("mma.sync.aligned.m16n8k16.row.col.f32.bf16.bf16.f32 " \
                 "{%0,%1,%2,%3}, {%4,%5,%6,%7}, {%8,%9}, {%0,%1,%2,%3};" \
                 : "+f"((c)[0]), "+f"((c)[1]), "+f"((c)[2]), "+f"((c)[3]) \
                 : "r"((a)[0]), "r"((a)[1]), "r"((a)[2]), "r"((a)[3]), \
                   "r"((b)[0]), "r"((b)[1]))

#define SMEM_SWIZZLE_128B(byte_offset) \
    ((byte_offset) ^ (((byte_offset) >> 3) & 0x70))

// ---------------------------------------------------------------------------
// GEMM: C = (Ahi + Alo) @ Bhi^T + Ahi @ Blo^T + bias
// CTA tile 128(M) x 256(N), BK=64; 8 warps 2(M)x4(N); warp tile 64x64.
// Stage: [A0 16KB][A1 16KB][B 32KB] = 64KB; 3-stage cp.async ring.
// Persistent CTAs + atomic ticket scheduler; fragment double-buffering.
// ---------------------------------------------------------------------------
#define STAGES 3
#define STAGE_BYTES 65536
#define GS_TOTAL (STAGES * STAGE_BYTES)   // 196608
#define NKT 16
#define NIT 32

__device__ __forceinline__ void gemm_issue_load(
    uint32_t sb, int slot, int tid, int m0, int n0, int k0,
    const __nv_bfloat16* __restrict__ A0, const __nv_bfloat16* __restrict__ A1,
    const __nv_bfloat16* __restrict__ B, int dual)
{
    uint32_t base = sb + slot * STAGE_BYTES;
    #pragma unroll
    for (int i = 0; i < 4; i++) {           // A0: 128 rows x 8 chunks
        int id = tid + (i << 8);
        int r  = id >> 3;
        int cc = id & 7;
        uint32_t soff = SMEM_SWIZZLE_128B((uint32_t)((r << 7) + (cc << 4)));
        cp16(base + soff, A0 + (size_t)(m0 + r) * DD_ + k0 + (cc << 3));
    }
    if (dual) {
        #pragma unroll
        for (int i = 0; i < 4; i++) {       // A1
            int id = tid + (i << 8);
            int r  = id >> 3;
            int cc = id & 7;
            uint32_t soff = SMEM_SWIZZLE_128B((uint32_t)((r << 7) + (cc << 4)));
            cp16(base + 16384 + soff, A1 + (size_t)(m0 + r) * DD_ + k0 + (cc << 3));
        }
    }
    #pragma unroll
    for (int i = 0; i < 8; i++) {           // B: 256 rows x 8 chunks
        int id = tid + (i << 8);
        int r  = id >> 3;
        int cc = id & 7;
        uint32_t soff = SMEM_SWIZZLE_128B((uint32_t)((r << 7) + (cc << 4)));
        cp16(base + 32768 + soff, B + (size_t)(n0 + r) * DD_ + k0 + (cc << 3));
    }
    CP_ASYNC_COMMIT();
}

__device__ __forceinline__ void gemm_pick_srcs(
    int it,
    const __nv_bfloat16* Ahi, const __nv_bfloat16* Alo,
    const __nv_bfloat16* Bhi, const __nv_bfloat16* Blo,
    const __nv_bfloat16** A0, const __nv_bfloat16** A1,
    const __nv_bfloat16** B, int* dual, int* k0)
{
    int phase = it >> 4;
    int kt = it & 15;
    *k0 = kt << 6;
    if (phase == 0) { *A0 = Ahi; *A1 = Alo; *B = Bhi; *dual = 1; }
    else            { *A0 = Ahi; *A1 = Ahi; *B = Blo; *dual = 0; }
}

__global__ __launch_bounds__(256, 1) void gemm3split_kernel(
    const __nv_bfloat16* __restrict__ Ahi, const __nv_bfloat16* __restrict__ Alo,
    const __nv_bfloat16* __restrict__ Bhi, const __nv_bfloat16* __restrict__ Blo,
    const float* __restrict__ bias, float* __restrict__ C, int N,
    unsigned int* __restrict__ ticket, int ntiles, int nblk)
{
    extern __shared__ char smem[];
    __shared__ unsigned int s_t;
    uint32_t sb = smem_to_u32(smem);
    const int tid = threadIdx.x;
    const int wid = tid >> 5;
    const int lane = tid & 31;
    const int warp_m = (wid & 1) * 64;
    const int warp_n = (wid >> 1) * 64;

    // ldmatrix per-lane address components (validated R2/R3)
    const int lr = lane & 7;
    const int a_row = warp_m + lr + ((lane & 8) ? 8 : 0);
    const int a_ksel = (lane & 16) ? 16 : 0;
    const int b_row = warp_n + lr + ((lane & 16) ? 8 : 0);
    const int b_ksel = (lane & 8) ? 16 : 0;

    for (;;) {
        __syncthreads();   // protect s_t + smem reuse from previous tile
        if (tid == 0) s_t = atomicAdd(ticket, 1u);
        __syncthreads();
        unsigned int t = s_t;
        if (t >= (unsigned int)ntiles) break;
        const int n0 = (int)(t % (unsigned int)nblk) * 256;
        const int m0 = (int)(t / (unsigned int)nblk) * 128;

        float acc[4][8][4];
        #pragma unroll
        for (int i = 0; i < 4; i++)
            #pragma unroll
            for (int j = 0; j < 8; j++)
                #pragma unroll
                for (int k = 0; k < 4; k++) acc[i][j][k] = 0.0f;

        // prologue: stages 0,1
        {
            const __nv_bfloat16 *A0, *A1, *B; int dual, k0;
            gemm_pick_srcs(0, Ahi, Alo, Bhi, Blo, &A0, &A1, &B, &dual, &k0);
            gemm_issue_load(sb, 0, tid, m0, n0, k0, A0, A1, B, dual);
            gemm_pick_srcs(1, Ahi, Alo, Bhi, Blo, &A0, &A1, &B, &dual, &k0);
            gemm_issue_load(sb, 1, tid, m0, n0, k0, A0, A1, B, dual);
        }

        int slot = 0;
        for (int it = 0; it < NIT; it++) {
            if (it == NIT - 1) { CP_ASYNC_WAIT_0(); } else { CP_ASYNC_WAIT_1(); }
            __syncthreads();

            int nt = it + 2;
            if (nt < NIT) {
                const __nv_bfloat16 *A0, *A1, *B; int dual, k0;
                gemm_pick_srcs(nt, Ahi, Alo, Bhi, Blo, &A0, &A1, &B, &dual, &k0);
                int ns = slot + 2; if (ns >= STAGES) ns -= STAGES;
                gemm_issue_load(sb, ns, tid, m0, n0, k0, A0, A1, B, dual);
            }

            uint32_t ab = sb + slot * STAGE_BYTES;
            uint32_t bb = ab + 32768;
            const int dual_c = (it < NKT);

            // fragment double buffers across ks
            uint32_t bfr[2][8][2];
            uint32_t afr[2][4][4];
            uint32_t afr2[4][4];

            // preload ks=0 into buffer 0
            #pragma unroll
            for (int nb = 0; nb < 4; nb++) {
                int row = b_row + nb * 16;
                uint32_t addr = bb + (uint32_t)(row << 7)
                              + (uint32_t)((b_ksel) ^ ((row & 7) << 4));
                LDSM_X4(bfr[0][2 * nb][0], bfr[0][2 * nb][1],
                        bfr[0][2 * nb + 1][0], bfr[0][2 * nb + 1][1], addr);
            }
            #pragma unroll
            for (int mf = 0; mf < 4; mf++) {
                int row = a_row + mf * 16;
                uint32_t addr = ab + (uint32_t)(row << 7)
                              + (uint32_t)((a_ksel) ^ ((row & 7) << 4));
                LDSM_X4(afr[0][mf][0], afr[0][mf][1], afr[0][mf][2], afr[0][mf][3], addr);
            }

            #pragma unroll
            for (int ks = 0; ks < 4; ks++) {
                const int p = ks & 1;
                const int q = p ^ 1;
                // A2 (lo) fragments for this ks
                if (dual_c) {
                    #pragma unroll
                    for (int mf = 0; mf < 4; mf++) {
                        int row = a_row + mf * 16;
                        uint32_t addr = ab + 16384 + (uint32_t)(row << 7)
                                      + (uint32_t)(((ks << 5) + a_ksel) ^ ((row & 7) << 4));
                        LDSM_X4(afr2[mf][0], afr2[mf][1], afr2[mf][2], afr2[mf][3], addr);
                    }
                }
                // prefetch next ks fragments
                if (ks < 3) {
                    #pragma unroll
                    for (int nb = 0; nb < 4; nb++) {
                        int row = b_row + nb * 16;
                        uint32_t addr = bb + (uint32_t)(row << 7)
                                      + (uint32_t)((((ks + 1) << 5) + b_ksel) ^ ((row & 7) << 4));
                        LDSM_X4(bfr[q][2 * nb][0], bfr[q][2 * nb][1],
                                bfr[q][2 * nb + 1][0], bfr[q][2 * nb + 1][1], addr);
                    }
                    #pragma unroll
                    for (int mf = 0; mf < 4; mf++) {
                        int row = a_row + mf * 16;
                        uint32_t addr = ab + (uint32_t)(row << 7)
                                      + (uint32_t)((((ks + 1) << 5) + a_ksel) ^ ((row & 7) << 4));
                        LDSM_X4(afr[q][mf][0], afr[q][mf][1], afr[q][mf][2], afr[q][mf][3], addr);
                    }
                }
                // MMA block 1: Ahi-part
                #pragma unroll
                for (int mf = 0; mf < 4; mf++)
                    #pragma unroll
                    for (int nf = 0; nf < 8; nf++)
                        MMA_16816(acc[mf][nf], afr[p][mf], bfr[p][nf]);
                // MMA block 2: Alo-part (dual phase)
                if (dual_c) {
                    #pragma unroll
                    for (int mf = 0; mf < 4; mf++)
                        #pragma unroll
                        for (int nf = 0; nf < 8; nf++)
                            MMA_16816(acc[mf][nf], afr2[mf], bfr[p][nf]);
                }
            }
            slot++; if (slot >= STAGES) slot = 0;
        }

        // epilogue: regs -> gmem with bias
        const int gid = lane >> 2;
        const int t4 = lane & 3;
        #pragma unroll
        for (int mf = 0; mf < 4; mf++) {
            int r0 = m0 + warp_m + mf * 16 + gid;
            #pragma unroll
            for (int nf = 0; nf < 8; nf++) {
                int c = n0 + warp_n + nf * 8 + t4 * 2;
                float2 b2 = *(const float2*)(bias + c);
                float2 v0 = make_float2(acc[mf][nf][0] + b2.x, acc[mf][nf][1] + b2.y);
                float2 v1 = make_float2(acc[mf][nf][2] + b2.x, acc[mf][nf][3] + b2.y);
                *(float2*)(C + (size_t)r0 * N + c) = v0;
                *(float2*)(C + (size_t)(r0 + 8) * N + c) = v1;
            }
        }
    }
}

// ---------------------------------------------------------------------------
// Elementwise / reduction kernels
// ---------------------------------------------------------------------------
__global__ void cvt_hilo_kernel(const float* __restrict__ in,
                                __nv_bfloat16* __restrict__ hi,
                                __nv_bfloat16* __restrict__ lo, int n4)
{
    int idx = blockIdx.x * blockDim.x + threadIdx.x;
    if (idx >= n4) return;
    float4 v = ((const float4*)in)[idx];
    __nv_bfloat16 h0 = __float2bfloat16(v.x);
    __nv_bfloat16 h1 = __float2bfloat16(v.y);
    __nv_bfloat16 h2 = __float2bfloat16(v.z);
    __nv_bfloat16 h3 = __float2bfloat16(v.w);
    __nv_bfloat16 l0 = __float2bfloat16(v.x - __bfloat162float(h0));
    __nv_bfloat16 l1 = __float2bfloat16(v.y - __bfloat162float(h1));
    __nv_bfloat16 l2 = __float2bfloat16(v.z - __bfloat162float(h2));
    __nv_bfloat16 l3 = __float2bfloat16(v.w - __bfloat162float(h3));
    ((__nv_bfloat162*)hi)[idx * 2 + 0] = __halves2bfloat162(h0, h1);
    ((__nv_bfloat162*)hi)[idx * 2 + 1] = __halves2bfloat162(h2, h3);
    ((__nv_bfloat162*)lo)[idx * 2 + 0] = __halves2bfloat162(l0, l1);
    ((__nv_bfloat162*)lo)[idx * 2 + 1] = __halves2bfloat162(l2, l3);
}

// zero kv + reset ticket counters (runs every graph replay, first launch)
__global__ void zero_misc_kernel(float* __restrict__ kv, unsigned int* __restrict__ ticket)
{
    int i = blockIdx.x * blockDim.x + threadIdx.x;
    if (i < BB_ * DD_) kv[i] = 0.0f;
    if (i < 2) ticket[i] = 0u;
}

__global__ void detect_mask_kernel(const unsigned char* __restrict__ m)
{
    __shared__ int any;
    if (threadIdx.x == 0) any = 0;
    __syncthreads();
    int acc = 0;
    for (int i = threadIdx.x; i < MM_; i += blockDim.x)
        if ((i & 3) != 0) acc |= m[i];
    if (acc) atomicOr(&any, 1);
    __syncthreads();
    if (threadIdx.x == 0) g_mask_is_byte = any ? 1 : 0;
}

__global__ __launch_bounds__(256) void stage2_kernel(
    const float* __restrict__ qkv, const unsigned char* __restrict__ mask,
    float* __restrict__ invq, float* __restrict__ kv)
{
    __shared__ float s_ik[32];
    int tid = threadIdx.x, lane = tid & 31, warp = tid >> 5;
    int R0 = blockIdx.x * 32;
    int b = R0 >> 12;
    int maskIsByte = g_mask_is_byte;
    const int* mask32 = (const int*)mask;

    #pragma unroll
    for (int rr = 0; rr < 4; rr++) {
        int row = R0 + warp * 4 + rr;
        const float4* base = (const float4*)(qkv + (size_t)row * E3_);
        float sq = 0.f, sk = 0.f;
        #pragma unroll
        for (int j = 0; j < 8; j++) {
            float4 q4 = base[lane + 32 * j];
            float4 k4 = base[256 + lane + 32 * j];
            sq += q4.x*q4.x + q4.y*q4.y + q4.z*q4.z + q4.w*q4.w;
            sk += k4.x*k4.x + k4.y*k4.y + k4.z*k4.z + k4.w*k4.w;
        }
        #pragma unroll
        for (int o = 16; o > 0; o >>= 1) {
            sq += __shfl_xor_sync(0xffffffffu, sq, o);
            sk += __shfl_xor_sync(0xffffffffu, sk, o);
        }
        if (lane == 0) {
            invq[row] = rsqrtf(sq);
            s_ik[warp * 4 + rr] = rsqrtf(sk);
        }
    }
    __syncthreads();

    float ax = 0.f, ay = 0.f, az = 0.f, aw = 0.f;
    for (int r = 0; r < 32; r++) {
        int row = R0 + r;
        bool msk = maskIsByte ? (mask[row] != 0) : (mask32[row] != 0);
        if (!msk) {
            float ik = s_ik[r];
            const float4* base = (const float4*)(qkv + (size_t)row * E3_);
            float4 k4 = base[256 + tid];
            float4 v4 = base[512 + tid];
            ax += k4.x * ik * v4.x;
            ay += k4.y * ik * v4.y;
            az += k4.z * ik * v4.z;
            aw += k4.w * ik * v4.w;
        }
    }
    float* kvb = kv + b * DD_ + tid * 4;
    atomicAdd(kvb + 0, ax);
    atomicAdd(kvb + 1, ay);
    atomicAdd(kvb + 2, az);
    atomicAdd(kvb + 3, aw);
}

__global__ __launch_bounds__(256) void stage3_kernel(
    const float* __restrict__ qkv, const float* __restrict__ invq,
    const float* __restrict__ kv,
    __nv_bfloat16* __restrict__ hi, __nv_bfloat16* __restrict__ lo)
{
    int idx = blockIdx.x * blockDim.x + threadIdx.x;
    int row = idx >> 8;
    int d4  = idx & 255;
    int b   = row >> 12;
    float4 q = *(const float4*)(qkv + (size_t)row * E3_ + d4 * 4);
    float s = invq[row];
    float4 kvv = *(const float4*)(kv + b * DD_ + d4 * 4);
    float a0 = q.x * s * kvv.x;
    float a1 = q.y * s * kvv.y;
    float a2 = q.z * s * kvv.z;
    float a3 = q.w * s * kvv.w;
    __nv_bfloat16 h0 = __float2bfloat16(a0);
    __nv_bfloat16 h1 = __float2bfloat16(a1);
    __nv_bfloat16 h2 = __float2bfloat16(a2);
    __nv_bfloat16 h3 = __float2bfloat16(a3);
    __nv_bfloat16 l0 = __float2bfloat16(a0 - __bfloat162float(h0));
    __nv_bfloat16 l1 = __float2bfloat16(a1 - __bfloat162float(h1));
    __nv_bfloat16 l2 = __float2bfloat16(a2 - __bfloat162float(h2));
    __nv_bfloat16 l3 = __float2bfloat16(a3 - __bfloat162float(h3));
    ((__nv_bfloat162*)hi)[idx * 2 + 0] = __halves2bfloat162(h0, h1);
    ((__nv_bfloat162*)hi)[idx * 2 + 1] = __halves2bfloat162(h2, h3);
    ((__nv_bfloat162*)lo)[idx * 2 + 0] = __halves2bfloat162(l0, l1);
    ((__nv_bfloat162*)lo)[idx * 2 + 1] = __halves2bfloat162(l2, l3);
}

// ---------------------------------------------------------------------------
// Launch
// ---------------------------------------------------------------------------
extern "C" void kernel_launch(void* const* d_in, const int* in_sizes, int n_in,
                              void* d_out, int out_size)
{
    const float* x = (const float*)d_in[0];
    const unsigned char* mask = (const unsigned char*)d_in[1];
    const float* Wqkv = (const float*)d_in[2];
    const float* bqkv = (const float*)d_in[3];
    const float* Wout = (const float*)d_in[4];
    const float* bout = (const float*)d_in[5];
    float* out = (float*)d_out;

    float *p_qkv, *p_invq, *p_kv;
    unsigned int* p_ticket;
    __nv_bfloat16 *p_xhi, *p_xlo, *p_wqhi, *p_wqlo, *p_wohi, *p_wolo;
    cudaGetSymbolAddress((void**)&p_qkv, g_qkv);
    cudaGetSymbolAddress((void**)&p_invq, g_invq);
    cudaGetSymbolAddress((void**)&p_kv, g_kv);
    cudaGetSymbolAddress((void**)&p_ticket, g_ticket);
    cudaGetSymbolAddress((void**)&p_xhi, g_x_hi);
    cudaGetSymbolAddress((void**)&p_xlo, g_x_lo);
    cudaGetSymbolAddress((void**)&p_wqhi, g_wq_hi);
    cudaGetSymbolAddress((void**)&p_wqlo, g_wq_lo);
    cudaGetSymbolAddress((void**)&p_wohi, g_wo_hi);
    cudaGetSymbolAddress((void**)&p_wolo, g_wo_lo);

    int nsm = 148;
    cudaDeviceGetAttribute(&nsm, cudaDevAttrMultiProcessorCount, 0);
    if (nsm <= 0) nsm = 148;

    cudaFuncSetAttribute(gemm3split_kernel,
                         cudaFuncAttributeMaxDynamicSharedMemorySize, GS_TOTAL);

    // Launch order tuned so ncu (-s 5 -c 1) captures GEMM1 at slot #4.
    // 1: zero kv + tickets
    zero_misc_kernel<<<(BB_ * DD_ + 255) / 256, 256>>>(p_kv, p_ticket);
    // 2,3: conversions needed by GEMM1
    cvt_hilo_kernel<<<(MM_ * DD_ / 4 + 255) / 256, 256>>>(x, p_xhi, p_xlo, MM_ * DD_ / 4);
    cvt_hilo_kernel<<<(E3_ * DD_ / 4 + 255) / 256, 256>>>(Wqkv, p_wqhi, p_wqlo, E3_ * DD_ / 4);
    // 4: GEMM1: qkv = x @ W_qkv^T + b_qkv   (16384 x 3072)
    gemm3split_kernel<<<nsm, 256, GS_TOTAL>>>(
        p_xhi, p_xlo, p_wqhi, p_wqlo, bqkv, p_qkv, E3_,
        p_ticket + 0, (MM_ / 128) * (E3_ / 256), E3_ / 256);
    // 5: W_out conversion (needed only by GEMM2)
    cvt_hilo_kernel<<<(DD_ * DD_ / 4 + 255) / 256, 256>>>(Wout, p_wohi, p_wolo, DD_ * DD_ / 4);
    // 6: mask dtype detection
    detect_mask_kernel<<<1, 512>>>(mask);
    // 7: norms + masked k_hat*v reduction
    stage2_kernel<<<MM_ / 32, 256>>>(p_qkv, mask, p_invq, p_kv);
    // 8: A2 = q_hat * kv -> bf16 hi/lo
    stage3_kernel<<<MM_ * DD_ / 4 / 256, 256>>>(p_qkv, p_invq, p_kv, p_xhi, p_xlo);
    // 9: GEMM2: out = A2 @ W_out^T + b_out   (16384 x 1024)
    gemm3split_kernel<<<nsm, 256, GS_TOTAL>>>(
        p_xhi, p_xlo, p_wohi, p_wolo, bout, out, DD_,
        p_ticket + 1, (MM_ / 128) * (DD_ / 256), DD_ / 256);
}

// round 5
// speedup vs baseline: 1.2429x; 1.2429x over previous
#include <cuda_runtime.h>
#include <cuda_bf16.h>
#include <cstdint>
#include <cstddef>

// ---------------------------------------------------------------------------
// Problem constants
// ---------------------------------------------------------------------------
#define BB_ 4
#define TT_ 4096
#define DD_ 1024
#define MM_ (BB_ * TT_)   // 16384 rows
#define E3_ (3 * DD_)     // 3072

// ---------------------------------------------------------------------------
// Scratch (static device globals -- allocation-free rule)
// ---------------------------------------------------------------------------
__device__ float g_qkv[(size_t)MM_ * E3_];
__device__ __nv_bfloat16 g_x_hi[(size_t)MM_ * DD_];        // reused as A2 hi
__device__ __nv_bfloat16 g_x_lo[(size_t)MM_ * DD_];        // reused as A2 lo
__device__ __nv_bfloat16 g_wq_hi[(size_t)E3_ * DD_];
__device__ __nv_bfloat16 g_wq_lo[(size_t)E3_ * DD_];
__device__ __nv_bfloat16 g_wo_hi[(size_t)DD_ * DD_];
__device__ __nv_bfloat16 g_wo_lo[(size_t)DD_ * DD_];
__device__ float g_invq[MM_];
__device__ float g_kv[BB_ * DD_];
__device__ int   g_mask_is_byte;

// ---------------------------------------------------------------------------
// Helpers (sm_103 baseline ISA: cp.async, ldmatrix, mma.sync)
// ---------------------------------------------------------------------------
__device__ __forceinline__ uint32_t smem_to_u32(const void* smem_ptr) {
    uint32_t addr;
    asm("{ .reg .u64 tmp; cvta.to.shared.u64 tmp, %1; cvt.u32.u64 %0, tmp; }"
        : "=r"(addr) : "l"(smem_ptr));
    return addr;
}

__device__ __forceinline__ void cp16(uint32_t smem_dst, const void* gmem_src) {
    asm volatile("cp.async.cg.shared.global [%0], [%1], 16;\n"
                 :: "r"(smem_dst), "l"(gmem_src));
}
#define CP_ASYNC_COMMIT() asm volatile("cp.async.commit_group;\n" ::: "memory")
#define CP_ASYNC_WAIT_1() asm volatile("cp.async.wait_group 1;\n" ::: "memory")
#define CP_ASYNC_WAIT_0() asm volatile("cp.async.wait_group 0;\n" ::: "memory")

#define LDSM_X4(r0, r1, r2, r3, addr) \
    asm volatile("ldmatrix.sync.aligned.m8n8.x4.shared.b16 {%0,%1,%2,%3}, [%4];" \
                 : "=r"(r0), "=r"(r1), "=r"(r2), "=r"(r3) : "r"(addr))

#define MMA_16816(c, a, b) \
    asm volatile("mma.sync.aligned.m16n8k16.row.col.f32.bf16.bf16.f32 " \
                 "{%0,%1,%2,%3}, {%4,%5,%6,%7}, {%8,%9}, {%0,%1,%2,%3};" \
                 : "+f"((c)[0]), "+f"((c)[1]), "+f"((c)[2]), "+f"((c)[3]) \
                 : "r"((a)[0]), "r"((a)[1]), "r"((a)[2]), "r"((a)[3]), \
                   "r"((b)[0]), "r"((b)[1]))

#define SMEM_SWIZZLE_128B(byte_offset) \
    ((byte_offset) ^ (((byte_offset) >> 3) & 0x70))

// ---------------------------------------------------------------------------
// GEMM: C = (Ahi + Alo) @ Bhi^T + Ahi @ Blo^T + bias
// CTA tile 128(M) x 256(N), BK=64; 512 threads = 16 warps 2(M)x8(N);
// warp tile 64x32 -> 4 warps per SMSP for latency hiding.
// Stage: [A0 16KB][A1 16KB][B 32KB] = 64KB; 3-stage cp.async ring (192KB).
// Phase 0 (it 0..15):  A0=Ahi, A1=Alo, B=Bhi  (dual-A, shared B)
// Phase 1 (it 16..31): A0=Ahi,        B=Blo  (single-A)
// ---------------------------------------------------------------------------
#define STAGES 3
#define STAGE_BYTES 65536
#define GS_TOTAL (STAGES * STAGE_BYTES)   // 196608
#define NKT 16
#define NIT 32
#define NTHR 512

__device__ __forceinline__ void gemm_issue_load(
    uint32_t sb, int slot, int tid, int m0, int n0, int k0,
    const __nv_bfloat16* __restrict__ A0, const __nv_bfloat16* __restrict__ A1,
    const __nv_bfloat16* __restrict__ B, int dual)
{
    uint32_t base = sb + slot * STAGE_BYTES;
    #pragma unroll
    for (int i = 0; i < 2; i++) {           // A0: 128 rows x 8 chunks = 1024
        int id = tid + (i << 9);
        int r  = id >> 3;
        int cc = id & 7;
        uint32_t soff = SMEM_SWIZZLE_128B((uint32_t)((r << 7) + (cc << 4)));
        cp16(base + soff, A0 + (size_t)(m0 + r) * DD_ + k0 + (cc << 3));
    }
    if (dual) {
        #pragma unroll
        for (int i = 0; i < 2; i++) {       // A1
            int id = tid + (i << 9);
            int r  = id >> 3;
            int cc = id & 7;
            uint32_t soff = SMEM_SWIZZLE_128B((uint32_t)((r << 7) + (cc << 4)));
            cp16(base + 16384 + soff, A1 + (size_t)(m0 + r) * DD_ + k0 + (cc << 3));
        }
    }
    #pragma unroll
    for (int i = 0; i < 4; i++) {           // B: 256 rows x 8 chunks = 2048
        int id = tid + (i << 9);
        int r  = id >> 3;
        int cc = id & 7;
        uint32_t soff = SMEM_SWIZZLE_128B((uint32_t)((r << 7) + (cc << 4)));
        cp16(base + 32768 + soff, B + (size_t)(n0 + r) * DD_ + k0 + (cc << 3));
    }
    CP_ASYNC_COMMIT();
}

__device__ __forceinline__ void gemm_pick_srcs(
    int it,
    const __nv_bfloat16* Ahi, const __nv_bfloat16* Alo,
    const __nv_bfloat16* Bhi, const __nv_bfloat16* Blo,
    const __nv_bfloat16** A0, const __nv_bfloat16** A1,
    const __nv_bfloat16** B, int* dual, int* k0)
{
    int phase = it >> 4;
    int kt = it & 15;
    *k0 = kt << 6;
    if (phase == 0) { *A0 = Ahi; *A1 = Alo; *B = Bhi; *dual = 1; }
    else            { *A0 = Ahi; *A1 = Ahi; *B = Blo; *dual = 0; }
}

__global__ __launch_bounds__(NTHR, 1) void gemm3split_kernel(
    const __nv_bfloat16* __restrict__ Ahi, const __nv_bfloat16* __restrict__ Alo,
    const __nv_bfloat16* __restrict__ Bhi, const __nv_bfloat16* __restrict__ Blo,
    const float* __restrict__ bias, float* __restrict__ C, int N)
{
    extern __shared__ char smem[];
    uint32_t sb = smem_to_u32(smem);
    const int tid = threadIdx.x;
    const int wid = tid >> 5;
    const int lane = tid & 31;
    const int n0 = blockIdx.x * 256;   // N fast-varying: wave shares A via L2
    const int m0 = blockIdx.y * 128;
    const int warp_m = (wid & 1) * 64;
    const int warp_n = (wid >> 1) * 32;

    // ldmatrix per-lane address components (validated R2-R4)
    const int lr = lane & 7;
    const int a_row = warp_m + lr + ((lane & 8) ? 8 : 0);
    const int a_ksel = (lane & 16) ? 16 : 0;
    const int b_row = warp_n + lr + ((lane & 16) ? 8 : 0);
    const int b_ksel = (lane & 8) ? 16 : 0;

    float acc[4][4][4];
    #pragma unroll
    for (int i = 0; i < 4; i++)
        #pragma unroll
        for (int j = 0; j < 4; j++)
            #pragma unroll
            for (int k = 0; k < 4; k++) acc[i][j][k] = 0.0f;

    // prologue: stages 0,1
    {
        const __nv_bfloat16 *A0, *A1, *B; int dual, k0;
        gemm_pick_srcs(0, Ahi, Alo, Bhi, Blo, &A0, &A1, &B, &dual, &k0);
        gemm_issue_load(sb, 0, tid, m0, n0, k0, A0, A1, B, dual);
        gemm_pick_srcs(1, Ahi, Alo, Bhi, Blo, &A0, &A1, &B, &dual, &k0);
        gemm_issue_load(sb, 1, tid, m0, n0, k0, A0, A1, B, dual);
    }

    int slot = 0;
    for (int it = 0; it < NIT; it++) {
        if (it == NIT - 1) { CP_ASYNC_WAIT_0(); } else { CP_ASYNC_WAIT_1(); }
        __syncthreads();

        int nt = it + 2;
        if (nt < NIT) {
            const __nv_bfloat16 *A0, *A1, *B; int dual, k0;
            gemm_pick_srcs(nt, Ahi, Alo, Bhi, Blo, &A0, &A1, &B, &dual, &k0);
            int ns = slot + 2; if (ns >= STAGES) ns -= STAGES;
            gemm_issue_load(sb, ns, tid, m0, n0, k0, A0, A1, B, dual);
        }

        uint32_t ab = sb + slot * STAGE_BYTES;
        uint32_t bb = ab + 32768;
        const int dual_c = (it < NKT);

        #pragma unroll
        for (int ks = 0; ks < 4; ks++) {
            // B fragments for this warp's 32 columns
            uint32_t bfr[4][2];
            #pragma unroll
            for (int nb = 0; nb < 2; nb++) {
                int row = b_row + nb * 16;
                uint32_t addr = bb + (uint32_t)(row << 7)
                              + (uint32_t)(((ks << 5) + b_ksel) ^ ((row & 7) << 4));
                LDSM_X4(bfr[2 * nb][0], bfr[2 * nb][1],
                        bfr[2 * nb + 1][0], bfr[2 * nb + 1][1], addr);
            }
            // A hi fragments
            uint32_t afr[4][4];
            #pragma unroll
            for (int mf = 0; mf < 4; mf++) {
                int row = a_row + mf * 16;
                uint32_t addr = ab + (uint32_t)(row << 7)
                              + (uint32_t)(((ks << 5) + a_ksel) ^ ((row & 7) << 4));
                LDSM_X4(afr[mf][0], afr[mf][1], afr[mf][2], afr[mf][3], addr);
            }
            #pragma unroll
            for (int mf = 0; mf < 4; mf++)
                #pragma unroll
                for (int nf = 0; nf < 4; nf++)
                    MMA_16816(acc[mf][nf], afr[mf], bfr[nf]);

            if (dual_c) {
                // A lo fragments (reuse afr registers)
                #pragma unroll
                for (int mf = 0; mf < 4; mf++) {
                    int row = a_row + mf * 16;
                    uint32_t addr = ab + 16384 + (uint32_t)(row << 7)
                                  + (uint32_t)(((ks << 5) + a_ksel) ^ ((row & 7) << 4));
                    LDSM_X4(afr[mf][0], afr[mf][1], afr[mf][2], afr[mf][3], addr);
                }
                #pragma unroll
                for (int mf = 0; mf < 4; mf++)
                    #pragma unroll
                    for (int nf = 0; nf < 4; nf++)
                        MMA_16816(acc[mf][nf], afr[mf], bfr[nf]);
            }
        }
        slot++; if (slot >= STAGES) slot = 0;
    }

    // epilogue: regs -> gmem with bias
    const int gid = lane >> 2;
    const int t4 = lane & 3;
    #pragma unroll
    for (int mf = 0; mf < 4; mf++) {
        int r0 = m0 + warp_m + mf * 16 + gid;
        #pragma unroll
        for (int nf = 0; nf < 4; nf++) {
            int c = n0 + warp_n + nf * 8 + t4 * 2;
            float2 b2 = *(const float2*)(bias + c);
            float2 v0 = make_float2(acc[mf][nf][0] + b2.x, acc[mf][nf][1] + b2.y);
            float2 v1 = make_float2(acc[mf][nf][2] + b2.x, acc[mf][nf][3] + b2.y);
            *(float2*)(C + (size_t)r0 * N + c) = v0;
            *(float2*)(C + (size_t)(r0 + 8) * N + c) = v1;
        }
    }
}

// ---------------------------------------------------------------------------
// Elementwise / reduction kernels
// ---------------------------------------------------------------------------
__global__ void cvt_hilo_kernel(const float* __restrict__ in,
                                __nv_bfloat16* __restrict__ hi,
                                __nv_bfloat16* __restrict__ lo, int n4)
{
    int idx = blockIdx.x * blockDim.x + threadIdx.x;
    if (idx >= n4) return;
    float4 v = ((const float4*)in)[idx];
    __nv_bfloat16 h0 = __float2bfloat16(v.x);
    __nv_bfloat16 h1 = __float2bfloat16(v.y);
    __nv_bfloat16 h2 = __float2bfloat16(v.z);
    __nv_bfloat16 h3 = __float2bfloat16(v.w);
    __nv_bfloat16 l0 = __float2bfloat16(v.x - __bfloat162float(h0));
    __nv_bfloat16 l1 = __float2bfloat16(v.y - __bfloat162float(h1));
    __nv_bfloat16 l2 = __float2bfloat16(v.z - __bfloat162float(h2));
    __nv_bfloat16 l3 = __float2bfloat16(v.w - __bfloat162float(h3));
    ((__nv_bfloat162*)hi)[idx * 2 + 0] = __halves2bfloat162(h0, h1);
    ((__nv_bfloat162*)hi)[idx * 2 + 1] = __halves2bfloat162(h2, h3);
    ((__nv_bfloat162*)lo)[idx * 2 + 0] = __halves2bfloat162(l0, l1);
    ((__nv_bfloat162*)lo)[idx * 2 + 1] = __halves2bfloat162(l2, l3);
}

__global__ void zero_kv_kernel(float* __restrict__ kv)
{
    int i = blockIdx.x * blockDim.x + threadIdx.x;
    if (i < BB_ * DD_) kv[i] = 0.0f;
}

__global__ void detect_mask_kernel(const unsigned char* __restrict__ m)
{
    __shared__ int any;
    if (threadIdx.x == 0) any = 0;
    __syncthreads();
    int acc = 0;
    for (int i = threadIdx.x; i < MM_; i += blockDim.x)
        if ((i & 3) != 0) acc |= m[i];
    if (acc) atomicOr(&any, 1);
    __syncthreads();
    if (threadIdx.x == 0) g_mask_is_byte = any ? 1 : 0;
}

__global__ __launch_bounds__(256) void stage2_kernel(
    const float* __restrict__ qkv, const unsigned char* __restrict__ mask,
    float* __restrict__ invq, float* __restrict__ kv)
{
    __shared__ float s_ik[32];
    int tid = threadIdx.x, lane = tid & 31, warp = tid >> 5;
    int R0 = blockIdx.x * 32;
    int b = R0 >> 12;
    int maskIsByte = g_mask_is_byte;
    const int* mask32 = (const int*)mask;

    #pragma unroll
    for (int rr = 0; rr < 4; rr++) {
        int row = R0 + warp * 4 + rr;
        const float4* base = (const float4*)(qkv + (size_t)row * E3_);
        float sq = 0.f, sk = 0.f;
        #pragma unroll
        for (int j = 0; j < 8; j++) {
            float4 q4 = base[lane + 32 * j];
            float4 k4 = base[256 + lane + 32 * j];
            sq += q4.x*q4.x + q4.y*q4.y + q4.z*q4.z + q4.w*q4.w;
            sk += k4.x*k4.x + k4.y*k4.y + k4.z*k4.z + k4.w*k4.w;
        }
        #pragma unroll
        for (int o = 16; o > 0; o >>= 1) {
            sq += __shfl_xor_sync(0xffffffffu, sq, o);
            sk += __shfl_xor_sync(0xffffffffu, sk, o);
        }
        if (lane == 0) {
            invq[row] = rsqrtf(sq);
            s_ik[warp * 4 + rr] = rsqrtf(sk);
        }
    }
    __syncthreads();

    float ax = 0.f, ay = 0.f, az = 0.f, aw = 0.f;
    for (int r = 0; r < 32; r++) {
        int row = R0 + r;
        bool msk = maskIsByte ? (mask[row] != 0) : (mask32[row] != 0);
        if (!msk) {
            float ik = s_ik[r];
            const float4* base = (const float4*)(qkv + (size_t)row * E3_);
            float4 k4 = base[256 + tid];
            float4 v4 = base[512 + tid];
            ax += k4.x * ik * v4.x;
            ay += k4.y * ik * v4.y;
            az += k4.z * ik * v4.z;
            aw += k4.w * ik * v4.w;
        }
    }
    float* kvb = kv + b * DD_ + tid * 4;
    atomicAdd(kvb + 0, ax);
    atomicAdd(kvb + 1, ay);
    atomicAdd(kvb + 2, az);
    atomicAdd(kvb + 3, aw);
}

__global__ __launch_bounds__(256) void stage3_kernel(
    const float* __restrict__ qkv, const float* __restrict__ invq,
    const float* __restrict__ kv,
    __nv_bfloat16* __restrict__ hi, __nv_bfloat16* __restrict__ lo)
{
    int idx = blockIdx.x * blockDim.x + threadIdx.x;
    int row = idx >> 8;
    int d4  = idx & 255;
    int b   = row >> 12;
    float4 q = *(const float4*)(qkv + (size_t)row * E3_ + d4 * 4);
    float s = invq[row];
    float4 kvv = *(const float4*)(kv + b * DD_ + d4 * 4);
    float a0 = q.x * s * kvv.x;
    float a1 = q.y * s * kvv.y;
    float a2 = q.z * s * kvv.z;
    float a3 = q.w * s * kvv.w;
    __nv_bfloat16 h0 = __float2bfloat16(a0);
    __nv_bfloat16 h1 = __float2bfloat16(a1);
    __nv_bfloat16 h2 = __float2bfloat16(a2);
    __nv_bfloat16 h3 = __float2bfloat16(a3);
    __nv_bfloat16 l0 = __float2bfloat16(a0 - __bfloat162float(h0));
    __nv_bfloat16 l1 = __float2bfloat16(a1 - __bfloat162float(h1));
    __nv_bfloat16 l2 = __float2bfloat16(a2 - __bfloat162float(h2));
    __nv_bfloat16 l3 = __float2bfloat16(a3 - __bfloat162float(h3));
    ((__nv_bfloat162*)hi)[idx * 2 + 0] = __halves2bfloat162(h0, h1);
    ((__nv_bfloat162*)hi)[idx * 2 + 1] = __halves2bfloat162(h2, h3);
    ((__nv_bfloat162*)lo)[idx * 2 + 0] = __halves2bfloat162(l0, l1);
    ((__nv_bfloat162*)lo)[idx * 2 + 1] = __halves2bfloat162(l2, l3);
}

// ---------------------------------------------------------------------------
// Launch
// ---------------------------------------------------------------------------
extern "C" void kernel_launch(void* const* d_in, const int* in_sizes, int n_in,
                              void* d_out, int out_size)
{
    const float* x = (const float*)d_in[0];
    const unsigned char* mask = (const unsigned char*)d_in[1];
    const float* Wqkv = (const float*)d_in[2];
    const float* bqkv = (const float*)d_in[3];
    const float* Wout = (const float*)d_in[4];
    const float* bout = (const float*)d_in[5];
    float* out = (float*)d_out;

    float *p_qkv, *p_invq, *p_kv;
    __nv_bfloat16 *p_xhi, *p_xlo, *p_wqhi, *p_wqlo, *p_wohi, *p_wolo;
    cudaGetSymbolAddress((void**)&p_qkv, g_qkv);
    cudaGetSymbolAddress((void**)&p_invq, g_invq);
    cudaGetSymbolAddress((void**)&p_kv, g_kv);
    cudaGetSymbolAddress((void**)&p_xhi, g_x_hi);
    cudaGetSymbolAddress((void**)&p_xlo, g_x_lo);
    cudaGetSymbolAddress((void**)&p_wqhi, g_wq_hi);
    cudaGetSymbolAddress((void**)&p_wqlo, g_wq_lo);
    cudaGetSymbolAddress((void**)&p_wohi, g_wo_hi);
    cudaGetSymbolAddress((void**)&p_wolo, g_wo_lo);

    cudaFuncSetAttribute(gemm3split_kernel,
                         cudaFuncAttributeMaxDynamicSharedMemorySize, GS_TOTAL);

    // Launch order keeps GEMM1 at ncu capture slot #4 (-s 5 -c 1).
    zero_kv_kernel<<<(BB_ * DD_ + 255) / 256, 256>>>(p_kv);
    cvt_hilo_kernel<<<(MM_ * DD_ / 4 + 255) / 256, 256>>>(x, p_xhi, p_xlo, MM_ * DD_ / 4);
    cvt_hilo_kernel<<<(E3_ * DD_ / 4 + 255) / 256, 256>>>(Wqkv, p_wqhi, p_wqlo, E3_ * DD_ / 4);
    // 4: GEMM1: qkv = x @ W_qkv^T + b_qkv   (16384 x 3072)
    gemm3split_kernel<<<dim3(E3_ / 256, MM_ / 128), NTHR, GS_TOTAL>>>(
        p_xhi, p_xlo, p_wqhi, p_wqlo, bqkv, p_qkv, E3_);
    cvt_hilo_kernel<<<(DD_ * DD_ / 4 + 255) / 256, 256>>>(Wout, p_wohi, p_wolo, DD_ * DD_ / 4);
    detect_mask_kernel<<<1, 512>>>(mask);
    stage2_kernel<<<MM_ / 32, 256>>>(p_qkv, mask, p_invq, p_kv);
    stage3_kernel<<<MM_ * DD_ / 4 / 256, 256>>>(p_qkv, p_invq, p_kv, p_xhi, p_xlo);
    // GEMM2: out = A2 @ W_out^T + b_out   (16384 x 1024)
    gemm3split_kernel<<<dim3(DD_ / 256, MM_ / 128), NTHR, GS_TOTAL>>>(
        p_xhi, p_xlo, p_wohi, p_wolo, bout, out, DD_);
}